// round 13
// baseline (speedup 1.0000x reference)
#include <cuda_runtime.h>

#define NN       50000
#define DIM      512
#define KMAX     32
#define NTHREADS 64

// Per-node state word: [63:32] = float eknew bits; bit0 = score ready; bit1 = row ready.
__device__ unsigned long long g_state[NN];
__device__ float g_eq[NN];    // feats[i].wq_w + wq_b
__device__ float g_ek0[NN];   // feats[i].wk_w + wk_b

__device__ __forceinline__ unsigned long long ld_relaxed_u64(const unsigned long long* p) {
    unsigned long long v;
    asm volatile("ld.global.relaxed.gpu.b64 %0, [%1];" : "=l"(v) : "l"(p) : "memory");
    return v;
}
__device__ __forceinline__ unsigned long long ld_acquire_u64(const unsigned long long* p) {
    unsigned long long v;
    asm volatile("ld.global.acquire.gpu.b64 %0, [%1];" : "=l"(v) : "l"(p) : "memory");
    return v;
}
__device__ __forceinline__ void st_relaxed_u64(unsigned long long* p, unsigned long long v) {
    asm volatile("st.global.relaxed.gpu.b64 [%0], %1;" :: "l"(p), "l"(v) : "memory");
}
__device__ __forceinline__ void st_release_u64(unsigned long long* p, unsigned long long v) {
    asm volatile("st.global.release.gpu.b64 [%0], %1;" :: "l"(p), "l"(v) : "memory");
}
__device__ __forceinline__ void v4_fma(float4& acc, float a, float4 v) {
    acc.x = fmaf(a, v.x, acc.x); acc.y = fmaf(a, v.y, acc.y);
    acc.z = fmaf(a, v.z, acc.z); acc.w = fmaf(a, v.w, acc.w);
}

// One warp per row: eq/ek0 GEMV for all nodes; reset state words. (No big fill!)
__global__ void pre_kernel(const float* __restrict__ feats,
                           const float* __restrict__ wq_w,
                           const float* __restrict__ wq_b,
                           const float* __restrict__ wk_w,
                           const float* __restrict__ wk_b)
{
    int gtid = blockIdx.x * blockDim.x + threadIdx.x;
    if (gtid < NN) g_state[gtid] = 0ull;

    int row_i = gtid >> 5;
    int lane  = gtid & 31;
    if (row_i >= NN) return;

    const float4* row = (const float4*)(feats + (size_t)row_i * DIM);
    const float4* q4  = (const float4*)wq_w;
    const float4* k4  = (const float4*)wk_w;
    float sq = 0.f, sk = 0.f;
    #pragma unroll
    for (int j = lane; j < DIM / 4; j += 32) {
        float4 f = row[j];
        float4 q = q4[j];
        float4 k = k4[j];
        sq += f.x*q.x + f.y*q.y + f.z*q.z + f.w*q.w;
        sk += f.x*k.x + f.y*k.y + f.z*k.z + f.w*k.w;
    }
    #pragma unroll
    for (int o = 16; o > 0; o >>= 1) {
        sq += __shfl_down_sync(0xffffffffu, sq, o);
        sk += __shfl_down_sync(0xffffffffu, sk, o);
    }
    if (lane == 0) {
        g_eq[row_i]  = sq + *wq_b;
        g_ek0[row_i] = sk + *wk_b;
    }
}

__global__ void __launch_bounds__(NTHREADS, 24)
attn_kernel(const float* __restrict__ feats,
            const int*   __restrict__ neighbors,
            const int*   __restrict__ deg,
            const float* __restrict__ wk_b,
            float*       out)
{
    __shared__ float        s_a[KMAX];          // early rows [0,nE), late [nE,nV)
    __shared__ const float* s_p[KMAX];
    __shared__ int          s_cnt;

    const int i    = blockIdx.x;
    const int tid  = threadIdx.x;
    const int b0   = tid * 4;                   // first owned segment
    const int b1   = tid * 4 + 256;             // second owned segment
    const int d    = deg[i];

    // ---- prefetch center row (independent of all waits) ----
    const float* fi = feats + (size_t)i * DIM;
    float4 accA = __ldg((const float4*)(fi + b0));
    float4 accB = __ldg((const float4*)(fi + b1));

    // per-lane early-neighbor state (lives in warp-0 registers across phases)
    bool  poll_early = false;
    int   nb_reg     = 0;
    float ekn_reg    = 0.f;                     // tid 0 only

    if (tid < 32) {
        const bool valid = tid < d;
        bool  early = false;
        float ej    = 0.f;
        if (valid) {
            nb_reg = neighbors[i * KMAX + tid];
            early  = nb_reg < i;
            if (early) {
                // score wait: payload packed in the state word; hot spin
                unsigned long long w;
                int it = 0;
                while (!((w = ld_relaxed_u64(&g_state[nb_reg])) & 1ull)) {
                    if (++it > 64) __nanosleep(20);
                }
                ej = __uint_as_float((unsigned)(w >> 32));
            } else {
                ej = __ldg(&g_ek0[nb_reg]);
            }
        }
        poll_early = valid && early;

        // ---- softmax (no max-subtract: scores O(1), identical math in fp32) ----
        const float wkb = *wk_b;
        const float ei  = __ldg(&g_eq[i]);
        float ex  = valid ? __expf(ei * ej) : 0.f;
        float s   = ex;
        float num = ex * (ej - wkb);
        #pragma unroll
        for (int o = 16; o > 0; o >>= 1) {
            s   += __shfl_xor_sync(0xffffffffu, s, o);
            num += __shfl_xor_sync(0xffffffffu, num, o);
        }

        // ---- publish score IMMEDIATELY (before any row work) ----
        if (tid == 0) {
            ekn_reg = __ldg(&g_ek0[i]) + ((d > 0) ? num / s : 0.f);
            unsigned long long w =
                ((unsigned long long)__float_as_uint(ekn_reg) << 32) | 1ull;
            st_relaxed_u64(&g_state[i], w);
        }

        // ---- compact: early rows first, then late ----
        unsigned vm = __ballot_sync(0xffffffffu, valid);
        unsigned em = __ballot_sync(0xffffffffu, poll_early);
        unsigned lm = vm & ~em;
        int nE_tot  = __popc(em);
        if (valid) {
            float a = ex / s;
            const float* p = (early ? out : feats) + (size_t)nb_reg * DIM;
            unsigned below = (1u << tid) - 1u;
            int k = early ? __popc(em & below) : nE_tot + __popc(lm & below);
            s_a[k] = a;
            s_p[k] = p;
        }
        if (tid == 0) s_cnt = nE_tot | (__popc(vm) << 16);
    }
    __syncthreads();

    const int nE = s_cnt & 0xffff;
    const int nV = s_cnt >> 16;

    // ---- late rows first (guaranteed ready; gives producers time) ----
    #pragma unroll 2
    for (int k = nE; k < nV; k++) {
        const float  a = s_a[k];
        const float* r = s_p[k];
        float4 vA = __ldg((const float4*)(r + b0));
        float4 vB = __ldg((const float4*)(r + b1));
        v4_fma(accA, a, vA);
        v4_fma(accB, a, vB);
    }

    // ---- row wait: warp-0 lanes acquire-poll their early neighbor's state ----
    if (poll_early) {
        int it = 0;
        while (!(ld_acquire_u64(&g_state[nb_reg]) & 2ull)) {
            if (++it > 64) __nanosleep(20);
        }
    }
    __syncthreads();   // extends the acquires CTA-wide

    // ---- early rows: plain L1-cacheable vector loads (post-acquire, safe) ----
    #pragma unroll 2
    for (int k = 0; k < nE; k++) {
        const float  a = s_a[k];
        const float* r = s_p[k];
        float4 vA = __ldg((const float4*)(r + b0));
        float4 vB = __ldg((const float4*)(r + b1));
        v4_fma(accA, a, vA);
        v4_fma(accB, a, vB);
    }

    // ---- publish row: plain stores -> bar -> release upgrade of state word ----
    float* oi = out + (size_t)i * DIM;
    *(float4*)(oi + b0) = accA;
    *(float4*)(oi + b1) = accB;
    __syncthreads();   // all threads' row stores ordered before tid0's release
    if (tid == 0) {
        unsigned long long w =
            ((unsigned long long)__float_as_uint(ekn_reg) << 32) | 3ull;
        st_release_u64(&g_state[i], w);
    }
}

extern "C" void kernel_launch(void* const* d_in, const int* in_sizes, int n_in,
                              void* d_out, int out_size) {
    const float* feats     = (const float*)d_in[0];
    const float* wq_w      = (const float*)d_in[1];
    const float* wq_b      = (const float*)d_in[2];
    const float* wk_w      = (const float*)d_in[3];
    const float* wk_b      = (const float*)d_in[4];
    const int*   neighbors = (const int*)d_in[5];
    const int*   deg       = (const int*)d_in[6];
    float*       out       = (float*)d_out;

    pre_kernel<<<(NN * 32) / 256, 256>>>(feats, wq_w, wq_b, wk_w, wk_b);
    attn_kernel<<<NN, NTHREADS>>>(feats, neighbors, deg, wk_b, out);
}

// round 14
// speedup vs baseline: 1.2820x; 1.2820x over previous
#include <cuda_runtime.h>

#define NN       50000
#define DIM      512
#define KMAX     32
#define NTHREADS 32
#define SENT     0x7FC00DADu   // NaN-payload sentinel: finite math can never produce it

// Score chain: packed word per node  [63:32]=float eknew bits, [31:0]=ready flag.
__device__ unsigned long long g_score[NN];
__device__ float g_eq[NN];    // feats[i].wq_w + wq_b
__device__ float g_ek0[NN];   // feats[i].wk_w + wk_b

__device__ __forceinline__ unsigned long long ld_relaxed_u64(const unsigned long long* p) {
    unsigned long long v;
    asm volatile("ld.global.relaxed.gpu.b64 %0, [%1];" : "=l"(v) : "l"(p) : "memory");
    return v;
}
__device__ __forceinline__ void st_relaxed_u64(unsigned long long* p, unsigned long long v) {
    asm volatile("st.global.relaxed.gpu.b64 [%0], %1;" :: "l"(p), "l"(v) : "memory");
}
__device__ __forceinline__ float4 ld_relaxed_v4(const float* p) {
    float4 v;
    asm volatile("ld.global.relaxed.gpu.v4.f32 {%0,%1,%2,%3}, [%4];"
                 : "=f"(v.x), "=f"(v.y), "=f"(v.z), "=f"(v.w) : "l"(p) : "memory");
    return v;
}
__device__ __forceinline__ void st_relaxed_v4(float* p, float4 v) {
    asm volatile("st.global.relaxed.gpu.v4.f32 [%0], {%1,%2,%3,%4};"
                 :: "l"(p), "f"(v.x), "f"(v.y), "f"(v.z), "f"(v.w) : "memory");
}
__device__ __forceinline__ bool v4_good(float4 v) {
    return (__float_as_uint(v.x) != SENT) & (__float_as_uint(v.y) != SENT) &
           (__float_as_uint(v.z) != SENT) & (__float_as_uint(v.w) != SENT);
}
__device__ __forceinline__ void v4_fma(float4& acc, float a, float4 v) {
    acc.x = fmaf(a, v.x, acc.x); acc.y = fmaf(a, v.y, acc.y);
    acc.z = fmaf(a, v.z, acc.z); acc.w = fmaf(a, v.w, acc.w);
}

// One warp per row: eq/ek0 GEMV; reset score flags; sentinel-fill ALL of out.
__global__ void pre_kernel(const float* __restrict__ feats,
                           const float* __restrict__ wq_w,
                           const float* __restrict__ wq_b,
                           const float* __restrict__ wk_w,
                           const float* __restrict__ wk_b,
                           float*       out)
{
    int gtid = blockIdx.x * blockDim.x + threadIdx.x;
    if (gtid < NN) g_score[gtid] = 0ull;

    // Sentinel-fill the whole out buffer (every word is its own readiness flag).
    {
        const unsigned s = SENT;
        float4 sv = make_float4(__uint_as_float(s), __uint_as_float(s),
                                __uint_as_float(s), __uint_as_float(s));
        float4* o4 = (float4*)out;
        const int total4 = NN * DIM / 4;          // 6.4M
        const int nthr   = (NN * 32);             // 1.6M threads
        for (int j = gtid; j < total4; j += nthr) o4[j] = sv;
    }

    int row_i = gtid >> 5;
    int lane  = gtid & 31;
    if (row_i >= NN) return;

    const float4* row = (const float4*)(feats + (size_t)row_i * DIM);
    const float4* q4  = (const float4*)wq_w;
    const float4* k4  = (const float4*)wk_w;
    float sq = 0.f, sk = 0.f;
    #pragma unroll
    for (int j = lane; j < DIM / 4; j += 32) {
        float4 f = row[j];
        float4 q = q4[j];
        float4 k = k4[j];
        sq += f.x*q.x + f.y*q.y + f.z*q.z + f.w*q.w;
        sk += f.x*k.x + f.y*k.y + f.z*k.z + f.w*k.w;
    }
    #pragma unroll
    for (int o = 16; o > 0; o >>= 1) {
        sq += __shfl_down_sync(0xffffffffu, sq, o);
        sk += __shfl_down_sync(0xffffffffu, sk, o);
    }
    if (lane == 0) {
        g_eq[row_i]  = sq + *wq_b;
        g_ek0[row_i] = sk + *wk_b;
    }
}

// One warp per node; each thread owns 4 strided float4 segments (16 floats).
__global__ void __launch_bounds__(NTHREADS, 28)
attn_kernel(const float* __restrict__ feats,
            const int*   __restrict__ neighbors,
            const int*   __restrict__ deg,
            const float* __restrict__ wk_b,
            float*       out)
{
    __shared__ float        s_a[KMAX];          // early rows [0,nE), late [nE,nV)
    __shared__ const float* s_p[KMAX];

    const int i   = blockIdx.x;
    const int tid = threadIdx.x;
    const int b0  = tid * 4;
    const int b1  = tid * 4 + 128;
    const int b2  = tid * 4 + 256;
    const int b3  = tid * 4 + 384;
    const int d   = deg[i];

    // ---- prefetch center row (independent of all waits) ----
    const float* fi = feats + (size_t)i * DIM;
    float4 accA = __ldg((const float4*)(fi + b0));
    float4 accB = __ldg((const float4*)(fi + b1));
    float4 accC = __ldg((const float4*)(fi + b2));
    float4 accD = __ldg((const float4*)(fi + b3));

    // ---- score phase (whole CTA = one warp) ----
    const bool valid = tid < d;
    int   nb    = 0;
    bool  early = false;
    float ej    = 0.f;
    if (valid) {
        nb    = neighbors[i * KMAX + tid];
        early = nb < i;
        if (early) {
            unsigned long long w;
            int it = 0;
            while ((unsigned)((w = ld_relaxed_u64(&g_score[nb]))) == 0u) {
                if (++it > 64) __nanosleep(20);
            }
            ej = __uint_as_float((unsigned)(w >> 32));
        } else {
            ej = __ldg(&g_ek0[nb]);
        }
    }

    // softmax (no max-subtract: scores O(1), identical math in fp32)
    const float wkb = *wk_b;
    const float ei  = __ldg(&g_eq[i]);
    float ex  = valid ? __expf(ei * ej) : 0.f;
    float s   = ex;
    float num = ex * (ej - wkb);
    #pragma unroll
    for (int o = 16; o > 0; o >>= 1) {
        s   += __shfl_xor_sync(0xffffffffu, s, o);
        num += __shfl_xor_sync(0xffffffffu, num, o);
    }

    // publish score IMMEDIATELY (before any row work)
    if (tid == 0) {
        float ekn = __ldg(&g_ek0[i]) + ((d > 0) ? num / s : 0.f);
        unsigned long long w =
            ((unsigned long long)__float_as_uint(ekn) << 32) | 1ull;
        st_relaxed_u64(&g_score[i], w);
    }

    // compact: early rows first, then late (registers via ballot)
    unsigned vm = __ballot_sync(0xffffffffu, valid);
    unsigned em = __ballot_sync(0xffffffffu, valid && early);
    unsigned lm = vm & ~em;
    const int nE = __popc(em);
    const int nV = __popc(vm);
    if (valid) {
        float a = ex / s;
        const float* p = (early ? out : feats) + (size_t)nb * DIM;
        unsigned below = (1u << tid) - 1u;
        int k = early ? __popc(em & below) : nE + __popc(lm & below);
        s_a[k] = a;
        s_p[k] = p;
    }
    __syncwarp();

    // ---- late rows first (guaranteed ready; gives producers time) ----
    for (int k = nE; k < nV; k++) {
        const float  a = s_a[k];
        const float* r = s_p[k];
        float4 vA = __ldg((const float4*)(r + b0));
        float4 vB = __ldg((const float4*)(r + b1));
        float4 vC = __ldg((const float4*)(r + b2));
        float4 vD = __ldg((const float4*)(r + b3));
        v4_fma(accA, a, vA);
        v4_fma(accB, a, vB);
        v4_fma(accC, a, vC);
        v4_fma(accD, a, vD);
    }

    // ---- early rows: four relaxed v4 per row, per-segment straggler masks ----
    unsigned badA = 0, badB = 0, badC = 0, badD = 0;
    for (int k = 0; k < nE; k++) {
        const float* p = s_p[k];
        float4 vA = ld_relaxed_v4(p + b0);
        float4 vB = ld_relaxed_v4(p + b1);
        float4 vC = ld_relaxed_v4(p + b2);
        float4 vD = ld_relaxed_v4(p + b3);
        const float a = s_a[k];
        if (v4_good(vA)) v4_fma(accA, a, vA); else badA |= 1u << k;
        if (v4_good(vB)) v4_fma(accB, a, vB); else badB |= 1u << k;
        if (v4_good(vC)) v4_fma(accC, a, vC); else badC |= 1u << k;
        if (v4_good(vD)) v4_fma(accD, a, vD); else badD |= 1u << k;
    }
    // retry ONLY straggler segments
    while (badA | badB | badC | badD) {
        unsigned m = badA;
        while (m) {
            int k = __ffs(m) - 1; m &= m - 1;
            float4 v = ld_relaxed_v4(s_p[k] + b0);
            if (v4_good(v)) { v4_fma(accA, s_a[k], v); badA &= ~(1u << k); }
        }
        m = badB;
        while (m) {
            int k = __ffs(m) - 1; m &= m - 1;
            float4 v = ld_relaxed_v4(s_p[k] + b1);
            if (v4_good(v)) { v4_fma(accB, s_a[k], v); badB &= ~(1u << k); }
        }
        m = badC;
        while (m) {
            int k = __ffs(m) - 1; m &= m - 1;
            float4 v = ld_relaxed_v4(s_p[k] + b2);
            if (v4_good(v)) { v4_fma(accC, s_a[k], v); badC &= ~(1u << k); }
        }
        m = badD;
        while (m) {
            int k = __ffs(m) - 1; m &= m - 1;
            float4 v = ld_relaxed_v4(s_p[k] + b3);
            if (v4_good(v)) { v4_fma(accD, s_a[k], v); badD &= ~(1u << k); }
        }
        if (badA | badB | badC | badD) __nanosleep(30);
    }

    // ---- publish row: relaxed v4 stores; every word carries its own flag ----
    float* oi = out + (size_t)i * DIM;
    st_relaxed_v4(oi + b0, accA);
    st_relaxed_v4(oi + b1, accB);
    st_relaxed_v4(oi + b2, accC);
    st_relaxed_v4(oi + b3, accD);
}

extern "C" void kernel_launch(void* const* d_in, const int* in_sizes, int n_in,
                              void* d_out, int out_size) {
    const float* feats     = (const float*)d_in[0];
    const float* wq_w      = (const float*)d_in[1];
    const float* wq_b      = (const float*)d_in[2];
    const float* wk_w      = (const float*)d_in[3];
    const float* wk_b      = (const float*)d_in[4];
    const int*   neighbors = (const int*)d_in[5];
    const int*   deg       = (const int*)d_in[6];
    float*       out       = (float*)d_out;

    pre_kernel<<<(NN * 32) / 256, 256>>>(feats, wq_w, wq_b, wk_w, wk_b, out);
    attn_kernel<<<NN, NTHREADS>>>(feats, neighbors, deg, wk_b, out);
}